// round 12
// baseline (speedup 1.0000x reference)
#include <cuda_runtime.h>
#include <cuda_bf16.h>
#include <cstdint>

#define NB    16
#define CIN   256
#define COUT  128
#define VRAW  10242
#define NVERT 40962
#define NROWS (NB * COUT)                 // 2048

#define BM    128
#define BNV   128
#define BK    32
#define NKCH  (CIN / BK)                  // 8
#define NVB   ((VRAW + BNV - 1) / BNV)    // 81

#define SC_GRID 148                       // persistent scatter CTAs (1/SM)

// Scratch (static __device__ — no allocation in kernel_launch)
__device__ float g_h[(size_t)NB * COUT * VRAW];   // 83.9 MB
__device__ int   g_nd[VRAW * 8];                  // 328 KB
__device__ __nv_bfloat16 g_Wh[COUT * CIN];
__device__ __nv_bfloat16 g_Wl[COUT * CIN];

// ---------------- gemm smem layout (bytes) ----------------
#define A_STRIDE 80
#define B_STRIDE 272
#define F_STRIDE 528
#define A_TILE   (BM * A_STRIDE)
#define B_TILE   (BK * B_STRIDE)
#define F_TILE   (BK * F_STRIDE)
#define OFF_A    0
#define OFF_B    (4 * A_TILE)
#define OFF_F    (OFF_B + 4 * B_TILE)
#define SMEM_TOTAL (OFF_F + 2 * F_TILE)   // 109568 (2 CTAs/SM)

// ---------------- scatter smem: win[] only ----------------
#define SC_SMEM (NVERT * 4 + 8)           // 163856

// ---------------------------------------------------------------------------
__device__ __forceinline__ uint32_t smem_u32(const void* p) {
    uint32_t a;
    asm("{ .reg .u64 t; cvta.to.shared.u64 t, %1; cvt.u32.u64 %0, t; }"
        : "=r"(a) : "l"(p));
    return a;
}
__device__ __forceinline__ void cpa16(uint32_t dst, const void* src) {
    asm volatile("cp.async.cg.shared.global [%0], [%1], 16;"
                 :: "r"(dst), "l"(src) : "memory");
}
__device__ __forceinline__ void cpa8(uint32_t dst, const void* src) {
    asm volatile("cp.async.ca.shared.global [%0], [%1], 8;"
                 :: "r"(dst), "l"(src) : "memory");
}
__device__ __forceinline__ void cpa8z(uint32_t dst, const void* src, uint32_t bytes) {
    asm volatile("cp.async.ca.shared.global [%0], [%1], 8, %2;"
                 :: "r"(dst), "l"(src), "r"(bytes) : "memory");
}
#define CP_COMMIT() asm volatile("cp.async.commit_group;" ::: "memory")
#define CP_WAIT(N)  asm volatile("cp.async.wait_group %0;" :: "n"(N) : "memory")

__device__ __forceinline__ void ldsm4(uint32_t* r, uint32_t addr) {
    asm volatile("ldmatrix.sync.aligned.m8n8.x4.shared.b16 {%0,%1,%2,%3}, [%4];"
                 : "=r"(r[0]), "=r"(r[1]), "=r"(r[2]), "=r"(r[3]) : "r"(addr));
}
__device__ __forceinline__ void ldsm4t(uint32_t* r, uint32_t addr) {
    asm volatile("ldmatrix.sync.aligned.m8n8.x4.trans.shared.b16 {%0,%1,%2,%3}, [%4];"
                 : "=r"(r[0]), "=r"(r[1]), "=r"(r[2]), "=r"(r[3]) : "r"(addr));
}
__device__ __forceinline__ void mma_bf16(float* c, const uint32_t* a,
                                         uint32_t b0, uint32_t b1) {
    asm volatile(
        "mma.sync.aligned.m16n8k16.row.col.f32.bf16.bf16.f32 "
        "{%0,%1,%2,%3}, {%4,%5,%6,%7}, {%8,%9}, {%0,%1,%2,%3};"
        : "+f"(c[0]), "+f"(c[1]), "+f"(c[2]), "+f"(c[3])
        : "r"(a[0]), "r"(a[1]), "r"(a[2]), "r"(a[3]), "r"(b0), "r"(b1));
}

// ---- cheap two-term split
__device__ __forceinline__ uint32_t pack_hi(float a, float b) {
    uint32_t r;
    asm("prmt.b32 %0, %1, %2, 0x7632;"
        : "=r"(r) : "r"(__float_as_uint(a)), "r"(__float_as_uint(b)));
    return r;
}
__device__ __forceinline__ float hi_f(float a) {
    return __uint_as_float(__float_as_uint(a) & 0xFFFF0000u);
}
__device__ __forceinline__ uint32_t pack_lo(float a, float b) {
    float la = a - hi_f(a), lb = b - hi_f(b);
    uint32_t r;
    asm("cvt.rn.bf16x2.f32 %0, %1, %2;" : "=r"(r) : "f"(lb), "f"(la));
    return r;
}

// ---------------------------------------------------------------------------
// Kernel 0: merged prep — blocks [0,16): split W; blocks [16,337): nd table
// ---------------------------------------------------------------------------
#define PREP_W_BLOCKS 16
__global__ __launch_bounds__(256) void prep_kernel(const float* __restrict__ W,
                                                   const int* __restrict__ up,
                                                   const int* __restrict__ down)
{
    if (blockIdx.x < PREP_W_BLOCKS) {
        int t = blockIdx.x * 256 + threadIdx.x;
        if (t >= COUT * CIN / 8) return;
        const float4* src = (const float4*)W + t * 2;
        float4 f0 = src[0], f1 = src[1];
        uint4 hi, lo;
        hi.x = pack_hi(f0.x, f0.y); lo.x = pack_lo(f0.x, f0.y);
        hi.y = pack_hi(f0.z, f0.w); lo.y = pack_lo(f0.z, f0.w);
        hi.z = pack_hi(f1.x, f1.y); lo.z = pack_lo(f1.x, f1.y);
        hi.w = pack_hi(f1.z, f1.w); lo.w = pack_lo(f1.z, f1.w);
        *(uint4*)(g_Wh + t * 8) = hi;
        *(uint4*)(g_Wl + t * 8) = lo;
    } else {
        int i = (blockIdx.x - PREP_W_BLOCKS) * 256 + threadIdx.x;
        if (i >= VRAW * 8) return;
        int v = i >> 3, k = i & 7;
        int val = 0;
        if (k < 7) val = up[down[v] * 7 + k];
        g_nd[i] = val;
    }
}

// ---------------------------------------------------------------------------
// Kernel 2: HMMA GEMM — single-barrier pipeline:
//   CP_WAIT ; convertB(buf) ; sync ; issue(kt+1 -> buf^1) ; compute(buf)
// Loads for kt+1 fly over the whole compute(kt). All cross-thread hazards are
// either buffer-disjoint or ordered by the single barrier (audit in header).
// ---------------------------------------------------------------------------
__global__ __launch_bounds__(256, 2)
void gemm_mma_kernel(const float* __restrict__ x, const float* __restrict__ bias)
{
    extern __shared__ char smem[];
    const uint32_t sbase = smem_u32(smem);
    const int tid  = threadIdx.x;
    const int lane = tid & 31;
    const int wid  = tid >> 5;
    const int b    = blockIdx.y;
    const int v0   = blockIdx.x * BNV;
    const int wo   = (wid >> 2) * 64;
    const int wv   = (wid & 3) * 32;
    const bool fullv = (v0 + BNV) <= VRAW;

    float acc[4][4][4];
    #pragma unroll
    for (int i = 0; i < 4; i++)
        #pragma unroll
        for (int j = 0; j < 4; j++)
            #pragma unroll
            for (int e = 0; e < 4; e++) acc[i][j][e] = 0.f;

    auto issueA = [&](int kc, int buf) {
        int o = tid >> 1, half = tid & 1;
        const __nv_bfloat16* sh = g_Wh + o * CIN + kc + half * 16;
        const __nv_bfloat16* sl = g_Wl + o * CIN + kc + half * 16;
        uint32_t dh = sbase + OFF_A + (buf * 2 + 0) * A_TILE + o * A_STRIDE + half * 32;
        uint32_t dl = dh + A_TILE;
        cpa16(dh, sh); cpa16(dh + 16, sh + 8);
        cpa16(dl, sl); cpa16(dl + 16, sl + 8);
    };
    auto issueF = [&](int kc, int fb) {
        int c = tid >> 3, seg = tid & 7;
        const float* src = x + ((size_t)(b * CIN + kc + c)) * VRAW + v0 + seg * 16;
        uint32_t dst = sbase + OFF_F + fb * F_TILE + c * F_STRIDE + seg * 64;
        if (fullv) {
            #pragma unroll
            for (int j = 0; j < 8; j++) cpa8(dst + j * 8, src + j * 2);
        } else {
            #pragma unroll
            for (int j = 0; j < 8; j++) {
                int gv = v0 + seg * 16 + j * 2;
                uint32_t bytes = (gv + 2 <= VRAW) ? 8u : 0u;
                cpa8z(dst + j * 8, bytes ? (src + j * 2) : x, bytes);
            }
        }
    };
    auto convertB = [&](int buf) {
        int c = tid >> 3, seg = tid & 7;
        const char* fp = smem + OFF_F + (buf & 1) * F_TILE + c * F_STRIDE + seg * 64;
        float4 q0 = *(const float4*)(fp);
        float4 q1 = *(const float4*)(fp + 16);
        float4 q2 = *(const float4*)(fp + 32);
        float4 q3 = *(const float4*)(fp + 48);
        uint4 hi0, lo0, hi1, lo1;
        hi0.x = pack_hi(q0.x, q0.y); lo0.x = pack_lo(q0.x, q0.y);
        hi0.y = pack_hi(q0.z, q0.w); lo0.y = pack_lo(q0.z, q0.w);
        hi0.z = pack_hi(q1.x, q1.y); lo0.z = pack_lo(q1.x, q1.y);
        hi0.w = pack_hi(q1.z, q1.w); lo0.w = pack_lo(q1.z, q1.w);
        hi1.x = pack_hi(q2.x, q2.y); lo1.x = pack_lo(q2.x, q2.y);
        hi1.y = pack_hi(q2.z, q2.w); lo1.y = pack_lo(q2.z, q2.w);
        hi1.z = pack_hi(q3.x, q3.y); lo1.z = pack_lo(q3.x, q3.y);
        hi1.w = pack_hi(q3.z, q3.w); lo1.w = pack_lo(q3.z, q3.w);
        char* bh = smem + OFF_B + (buf * 2 + 0) * B_TILE + c * B_STRIDE + seg * 32;
        char* bl = bh + B_TILE;
        *(uint4*)(bh)      = hi0;  *(uint4*)(bh + 16) = hi1;
        *(uint4*)(bl)      = lo0;  *(uint4*)(bl + 16) = lo1;
    };

    const int arow   = lane & 15;
    const int acol16 = (lane >> 4) * 16;
    const int brow   = ((lane >> 3) & 1) * 8 + (lane & 7);
    const int bcol16 = (lane >> 4) * 16;

    auto compute = [&](int buf) {
        uint32_t ah4 = sbase + OFF_A + (buf * 2) * A_TILE + (wo + arow) * A_STRIDE + acol16;
        uint32_t al4 = ah4 + A_TILE;
        uint32_t bh4 = sbase + OFF_B + (buf * 2) * B_TILE + brow * B_STRIDE + wv * 2 + bcol16;
        uint32_t bl4 = bh4 + B_TILE;
        #pragma unroll
        for (int ks = 0; ks < 2; ks++) {
            uint32_t a_h[4][4], a_l[4][4], b_h[2][4], b_l[2][4];
            #pragma unroll
            for (int mi = 0; mi < 4; mi++)
                ldsm4(a_h[mi], ah4 + mi * 16 * A_STRIDE + ks * 32);
            #pragma unroll
            for (int np = 0; np < 2; np++)
                ldsm4t(b_h[np], bh4 + ks * 16 * B_STRIDE + np * 32);
            #pragma unroll
            for (int np = 0; np < 2; np++)
                ldsm4t(b_l[np], bl4 + ks * 16 * B_STRIDE + np * 32);
            #pragma unroll
            for (int mi = 0; mi < 4; mi++)
                ldsm4(a_l[mi], al4 + mi * 16 * A_STRIDE + ks * 32);
            #pragma unroll
            for (int mi = 0; mi < 4; mi++)
                #pragma unroll
                for (int nj = 0; nj < 4; nj++)
                    mma_bf16(acc[mi][nj], a_h[mi],
                             b_h[nj >> 1][(nj & 1) * 2], b_h[nj >> 1][(nj & 1) * 2 + 1]);
            #pragma unroll
            for (int mi = 0; mi < 4; mi++)
                #pragma unroll
                for (int nj = 0; nj < 4; nj++)
                    mma_bf16(acc[mi][nj], a_h[mi],
                             b_l[nj >> 1][(nj & 1) * 2], b_l[nj >> 1][(nj & 1) * 2 + 1]);
            #pragma unroll
            for (int mi = 0; mi < 4; mi++)
                #pragma unroll
                for (int nj = 0; nj < 4; nj++)
                    mma_bf16(acc[mi][nj], a_l[mi],
                             b_h[nj >> 1][(nj & 1) * 2], b_h[nj >> 1][(nj & 1) * 2 + 1]);
        }
    };

    // prologue: chunk 0 in flight
    issueF(0, 0); issueA(0, 0); CP_COMMIT();

    for (int kt = 0; kt < NKCH; kt++) {
        int buf = kt & 1;
        CP_WAIT(0);              // F[buf], A[buf] landed
        convertB(buf);           // own F region -> B[buf]
        __syncthreads();         // B[buf] complete; all done with compute(kt-1)
        if (kt + 1 < NKCH) {
            issueF((kt + 1) * BK, buf ^ 1);
            issueA((kt + 1) * BK, buf ^ 1);
            CP_COMMIT();         // flies over compute(buf)
        }
        compute(buf);
    }

    #pragma unroll
    for (int mi = 0; mi < 4; mi++) {
        int o0 = wo + mi * 16 + (lane >> 2);
        float b0 = __ldg(&bias[o0]);
        float b1 = __ldg(&bias[o0 + 8]);
        float* h0 = g_h + ((size_t)b * COUT + o0) * VRAW;
        float* h1 = h0 + (size_t)8 * VRAW;
        #pragma unroll
        for (int nj = 0; nj < 4; nj++) {
            int gv = v0 + wv + nj * 8 + (lane & 3) * 2;
            if (gv < VRAW) {
                *(float2*)(h0 + gv) = make_float2(acc[mi][nj][0] + b0,
                                                  acc[mi][nj][1] + b0);
                *(float2*)(h1 + gv) = make_float2(acc[mi][nj][2] + b1,
                                                  acc[mi][nj][3] + b1);
            }
        }
    }
}

// ---------------------------------------------------------------------------
// Kernel 3: persistent scatter (R10 version — measured best at 120us).
// Epoch-encoded win (no reset pass), STG.128 write phase, __ldg h gather
// (hrow L1-resident; beats smem staging per R7/R11 measurements).
// ---------------------------------------------------------------------------
__global__ __launch_bounds__(1024, 1) void scatter_kernel(
    const int* __restrict__ mpi, float* __restrict__ y)
{
    extern __shared__ int win[];      // NVERT ints
    const int tid = threadIdx.x;

    // one-time zero (epoch starts at 1, so 0 never matches)
    {
        int4* w4 = (int4*)win;
        int4 z = make_int4(0, 0, 0, 0);
        #pragma unroll
        for (int i = 0; i < 10; i++) w4[tid + (i << 10)] = z;
        if (tid < 2) win[40960 + tid] = 0;
    }

    int row = blockIdx.x;
    int epoch = 1;
    int mk[11];
    {
        const int* mrow = mpi + (size_t)row * VRAW;
        #pragma unroll
        for (int i = 0; i < 11; i++) {
            int v = tid + (i << 10);
            mk[i] = (v < VRAW) ? __ldg(&mrow[v]) : 0;
        }
    }
    __syncthreads();

    while (row < NROWS) {
        const int tag = epoch << 14;
        // atomics phase
        #pragma unroll
        for (int i = 0; i < 11; i++) {
            int v = tid + (i << 10);
            if (v < VRAW) {
                int vert = g_nd[(v << 3) + mk[i]];
                atomicMax(&win[vert], tag | v);
            }
        }

        // prefetch next row's mpi (hides under write phase)
        int row2 = row + SC_GRID;
        int mk2[11];
        if (row2 < NROWS) {
            const int* mrow2 = mpi + (size_t)row2 * VRAW;
            #pragma unroll
            for (int i = 0; i < 11; i++) {
                int v = tid + (i << 10);
                mk2[i] = (v < VRAW) ? __ldg(&mrow2[v]) : 0;
            }
        }
        __syncthreads();   // atomics done before win reads

        // write phase: 10240 aligned float4 quads + one pair at the ragged end
        const float* hrow = g_h + (size_t)row * VRAW;
        float* yrow = y + (size_t)row * NVERT;
        const int s0 = (row & 1) ? 2 : 0;
        if (tid == 0) {
            int jp = (row & 1) ? 0 : 40960;
            int w0 = win[jp], w1 = win[jp + 1];
            float2 o;
            o.x = ((w0 >> 14) == epoch) ? __ldg(&hrow[w0 & 16383]) : 0.f;
            o.y = ((w1 >> 14) == epoch) ? __ldg(&hrow[w1 & 16383]) : 0.f;
            *(float2*)(yrow + jp) = o;
        }
        #pragma unroll
        for (int it = 0; it < 10; it++) {
            int q = tid + (it << 10);          // 0..10239
            int j = s0 + q * 4;
            int2 wa = *(const int2*)&win[j];
            int2 wb = *(const int2*)&win[j + 2];
            float4 o;
            o.x = ((wa.x >> 14) == epoch) ? __ldg(&hrow[wa.x & 16383]) : 0.f;
            o.y = ((wa.y >> 14) == epoch) ? __ldg(&hrow[wa.y & 16383]) : 0.f;
            o.z = ((wb.x >> 14) == epoch) ? __ldg(&hrow[wb.x & 16383]) : 0.f;
            o.w = ((wb.y >> 14) == epoch) ? __ldg(&hrow[wb.y & 16383]) : 0.f;
            *(float4*)(yrow + j) = o;
        }
        __syncthreads();   // win reads done before next row's atomics

        row = row2;
        epoch++;
        #pragma unroll
        for (int i = 0; i < 11; i++) mk[i] = mk2[i];
    }
}

// ---------------------------------------------------------------------------
extern "C" void kernel_launch(void* const* d_in, const int* in_sizes, int n_in,
                              void* d_out, int out_size)
{
    const float* x    = (const float*)d_in[0];
    const float* W    = (const float*)d_in[1];
    const float* bias = (const float*)d_in[2];
    const int*   up   = (const int*)d_in[3];
    const int*   down = (const int*)d_in[4];
    const int*   mpi  = (const int*)d_in[5];
    float* y = (float*)d_out;

    cudaFuncSetAttribute(scatter_kernel,
                         cudaFuncAttributeMaxDynamicSharedMemorySize, SC_SMEM);
    cudaFuncSetAttribute(gemm_mma_kernel,
                         cudaFuncAttributeMaxDynamicSharedMemorySize, SMEM_TOTAL);

    prep_kernel<<<PREP_W_BLOCKS + (VRAW * 8 + 255) / 256, 256>>>(W, up, down);

    dim3 g(NVB, NB);   // 81 x 16
    gemm_mma_kernel<<<g, 256, SMEM_TOTAL>>>(x, bias);

    scatter_kernel<<<SC_GRID, 1024, SC_SMEM>>>(mpi, y);
}

// round 13
// speedup vs baseline: 1.4581x; 1.4581x over previous
#include <cuda_runtime.h>
#include <cuda_bf16.h>
#include <cstdint>

#define NB    16
#define CIN   256
#define COUT  128
#define VRAW  10242
#define NVERT 40962
#define NROWS (NB * COUT)                 // 2048

#define BM    128
#define BNV   128
#define BK    32
#define NKCH  (CIN / BK)                  // 8
#define NVB   ((VRAW + BNV - 1) / BNV)    // 81

#define SC_GRID 148                       // persistent scatter CTAs (1/SM)

// Scratch (static __device__ — no allocation in kernel_launch)
__device__ float g_h[(size_t)NB * COUT * VRAW];   // 83.9 MB
__device__ int   g_nd[VRAW * 8];                  // 328 KB
__device__ __nv_bfloat16 g_Wh[COUT * CIN];
__device__ __nv_bfloat16 g_Wl[COUT * CIN];

// ---------------- gemm smem layout (bytes) ----------------
#define A_STRIDE 80
#define B_STRIDE 272
#define F_STRIDE 528
#define A_TILE   (BM * A_STRIDE)
#define B_TILE   (BK * B_STRIDE)
#define F_TILE   (BK * F_STRIDE)
#define OFF_A    0
#define OFF_B    (4 * A_TILE)
#define OFF_F    (OFF_B + 4 * B_TILE)
#define SMEM_TOTAL (OFF_F + 2 * F_TILE)   // 109568 (2 CTAs/SM)

// ---------------- scatter smem: win[] only ----------------
#define SC_SMEM (NVERT * 4 + 8)           // 163856

// ---------------------------------------------------------------------------
__device__ __forceinline__ uint32_t smem_u32(const void* p) {
    uint32_t a;
    asm("{ .reg .u64 t; cvta.to.shared.u64 t, %1; cvt.u32.u64 %0, t; }"
        : "=r"(a) : "l"(p));
    return a;
}
__device__ __forceinline__ void cpa16(uint32_t dst, const void* src) {
    asm volatile("cp.async.cg.shared.global [%0], [%1], 16;"
                 :: "r"(dst), "l"(src) : "memory");
}
__device__ __forceinline__ void cpa8(uint32_t dst, const void* src) {
    asm volatile("cp.async.ca.shared.global [%0], [%1], 8;"
                 :: "r"(dst), "l"(src) : "memory");
}
__device__ __forceinline__ void cpa8z(uint32_t dst, const void* src, uint32_t bytes) {
    asm volatile("cp.async.ca.shared.global [%0], [%1], 8, %2;"
                 :: "r"(dst), "l"(src), "r"(bytes) : "memory");
}
#define CP_COMMIT() asm volatile("cp.async.commit_group;" ::: "memory")
#define CP_WAIT(N)  asm volatile("cp.async.wait_group %0;" :: "n"(N) : "memory")

__device__ __forceinline__ void ldsm4(uint32_t* r, uint32_t addr) {
    asm volatile("ldmatrix.sync.aligned.m8n8.x4.shared.b16 {%0,%1,%2,%3}, [%4];"
                 : "=r"(r[0]), "=r"(r[1]), "=r"(r[2]), "=r"(r[3]) : "r"(addr));
}
__device__ __forceinline__ void ldsm4t(uint32_t* r, uint32_t addr) {
    asm volatile("ldmatrix.sync.aligned.m8n8.x4.trans.shared.b16 {%0,%1,%2,%3}, [%4];"
                 : "=r"(r[0]), "=r"(r[1]), "=r"(r[2]), "=r"(r[3]) : "r"(addr));
}
__device__ __forceinline__ void mma_bf16(float* c, const uint32_t* a,
                                         uint32_t b0, uint32_t b1) {
    asm volatile(
        "mma.sync.aligned.m16n8k16.row.col.f32.bf16.bf16.f32 "
        "{%0,%1,%2,%3}, {%4,%5,%6,%7}, {%8,%9}, {%0,%1,%2,%3};"
        : "+f"(c[0]), "+f"(c[1]), "+f"(c[2]), "+f"(c[3])
        : "r"(a[0]), "r"(a[1]), "r"(a[2]), "r"(a[3]), "r"(b0), "r"(b1));
}

// ---- cheap two-term split
__device__ __forceinline__ uint32_t pack_hi(float a, float b) {
    uint32_t r;
    asm("prmt.b32 %0, %1, %2, 0x7632;"
        : "=r"(r) : "r"(__float_as_uint(a)), "r"(__float_as_uint(b)));
    return r;
}
__device__ __forceinline__ float hi_f(float a) {
    return __uint_as_float(__float_as_uint(a) & 0xFFFF0000u);
}
__device__ __forceinline__ uint32_t pack_lo(float a, float b) {
    float la = a - hi_f(a), lb = b - hi_f(b);
    uint32_t r;
    asm("cvt.rn.bf16x2.f32 %0, %1, %2;" : "=r"(r) : "f"(lb), "f"(la));
    return r;
}

// ---------------------------------------------------------------------------
// Kernel 0: merged prep — blocks [0,16): split W; blocks [16,337): nd table
// ---------------------------------------------------------------------------
#define PREP_W_BLOCKS 16
__global__ __launch_bounds__(256) void prep_kernel(const float* __restrict__ W,
                                                   const int* __restrict__ up,
                                                   const int* __restrict__ down)
{
    if (blockIdx.x < PREP_W_BLOCKS) {
        int t = blockIdx.x * 256 + threadIdx.x;
        if (t >= COUT * CIN / 8) return;
        const float4* src = (const float4*)W + t * 2;
        float4 f0 = src[0], f1 = src[1];
        uint4 hi, lo;
        hi.x = pack_hi(f0.x, f0.y); lo.x = pack_lo(f0.x, f0.y);
        hi.y = pack_hi(f0.z, f0.w); lo.y = pack_lo(f0.z, f0.w);
        hi.z = pack_hi(f1.x, f1.y); lo.z = pack_lo(f1.x, f1.y);
        hi.w = pack_hi(f1.z, f1.w); lo.w = pack_lo(f1.z, f1.w);
        *(uint4*)(g_Wh + t * 8) = hi;
        *(uint4*)(g_Wl + t * 8) = lo;
    } else {
        int i = (blockIdx.x - PREP_W_BLOCKS) * 256 + threadIdx.x;
        if (i >= VRAW * 8) return;
        int v = i >> 3, k = i & 7;
        int val = 0;
        if (k < 7) val = up[down[v] * 7 + k];
        g_nd[i] = val;
    }
}

// ---------------------------------------------------------------------------
// Kernel 2: HMMA GEMM — R10 pipeline skeleton (issue at top, CP_WAIT(1),
// two barriers; proven 274.9us config). Only change: compute() interleaves
// ldsm with mma groups to shorten front latency and cut live registers.
// ---------------------------------------------------------------------------
__global__ __launch_bounds__(256, 2)
void gemm_mma_kernel(const float* __restrict__ x, const float* __restrict__ bias)
{
    extern __shared__ char smem[];
    const uint32_t sbase = smem_u32(smem);
    const int tid  = threadIdx.x;
    const int lane = tid & 31;
    const int wid  = tid >> 5;
    const int b    = blockIdx.y;
    const int v0   = blockIdx.x * BNV;
    const int wo   = (wid >> 2) * 64;
    const int wv   = (wid & 3) * 32;
    const bool fullv = (v0 + BNV) <= VRAW;

    float acc[4][4][4];
    #pragma unroll
    for (int i = 0; i < 4; i++)
        #pragma unroll
        for (int j = 0; j < 4; j++)
            #pragma unroll
            for (int e = 0; e < 4; e++) acc[i][j][e] = 0.f;

    auto issueA = [&](int kc, int buf) {
        int o = tid >> 1, half = tid & 1;
        const __nv_bfloat16* sh = g_Wh + o * CIN + kc + half * 16;
        const __nv_bfloat16* sl = g_Wl + o * CIN + kc + half * 16;
        uint32_t dh = sbase + OFF_A + (buf * 2 + 0) * A_TILE + o * A_STRIDE + half * 32;
        uint32_t dl = dh + A_TILE;
        cpa16(dh, sh); cpa16(dh + 16, sh + 8);
        cpa16(dl, sl); cpa16(dl + 16, sl + 8);
    };
    auto issueF = [&](int kc, int fb) {
        int c = tid >> 3, seg = tid & 7;
        const float* src = x + ((size_t)(b * CIN + kc + c)) * VRAW + v0 + seg * 16;
        uint32_t dst = sbase + OFF_F + fb * F_TILE + c * F_STRIDE + seg * 64;
        if (fullv) {
            #pragma unroll
            for (int j = 0; j < 8; j++) cpa8(dst + j * 8, src + j * 2);
        } else {
            #pragma unroll
            for (int j = 0; j < 8; j++) {
                int gv = v0 + seg * 16 + j * 2;
                uint32_t bytes = (gv + 2 <= VRAW) ? 8u : 0u;
                cpa8z(dst + j * 8, bytes ? (src + j * 2) : x, bytes);
            }
        }
    };
    auto convertB = [&](int buf) {
        int c = tid >> 3, seg = tid & 7;
        const char* fp = smem + OFF_F + (buf & 1) * F_TILE + c * F_STRIDE + seg * 64;
        float4 q0 = *(const float4*)(fp);
        float4 q1 = *(const float4*)(fp + 16);
        float4 q2 = *(const float4*)(fp + 32);
        float4 q3 = *(const float4*)(fp + 48);
        uint4 hi0, lo0, hi1, lo1;
        hi0.x = pack_hi(q0.x, q0.y); lo0.x = pack_lo(q0.x, q0.y);
        hi0.y = pack_hi(q0.z, q0.w); lo0.y = pack_lo(q0.z, q0.w);
        hi0.z = pack_hi(q1.x, q1.y); lo0.z = pack_lo(q1.x, q1.y);
        hi0.w = pack_hi(q1.z, q1.w); lo0.w = pack_lo(q1.z, q1.w);
        hi1.x = pack_hi(q2.x, q2.y); lo1.x = pack_lo(q2.x, q2.y);
        hi1.y = pack_hi(q2.z, q2.w); lo1.y = pack_lo(q2.z, q2.w);
        hi1.z = pack_hi(q3.x, q3.y); lo1.z = pack_lo(q3.x, q3.y);
        hi1.w = pack_hi(q3.z, q3.w); lo1.w = pack_lo(q3.z, q3.w);
        char* bh = smem + OFF_B + (buf * 2 + 0) * B_TILE + c * B_STRIDE + seg * 32;
        char* bl = bh + B_TILE;
        *(uint4*)(bh)      = hi0;  *(uint4*)(bh + 16) = hi1;
        *(uint4*)(bl)      = lo0;  *(uint4*)(bl + 16) = lo1;
    };

    const int arow   = lane & 15;
    const int acol16 = (lane >> 4) * 16;
    const int brow   = ((lane >> 3) & 1) * 8 + (lane & 7);
    const int bcol16 = (lane >> 4) * 16;

    auto compute = [&](int buf) {
        uint32_t ah4 = sbase + OFF_A + (buf * 2) * A_TILE + (wo + arow) * A_STRIDE + acol16;
        uint32_t al4 = ah4 + A_TILE;
        uint32_t bh4 = sbase + OFF_B + (buf * 2) * B_TILE + brow * B_STRIDE + wv * 2 + bcol16;
        uint32_t bl4 = bh4 + B_TILE;
        #pragma unroll
        for (int ks = 0; ks < 2; ks++) {
            uint32_t a_h[4][4], a_l[4][4], b_h[2][4], b_l[2][4];
            // front: only what the first mma group needs
            #pragma unroll
            for (int mi = 0; mi < 4; mi++)
                ldsm4(a_h[mi], ah4 + mi * 16 * A_STRIDE + ks * 32);
            #pragma unroll
            for (int np = 0; np < 2; np++)
                ldsm4t(b_h[np], bh4 + ks * 16 * B_STRIDE + np * 32);
            // group 1: hh — tensor work covers the b_l loads issued after
            #pragma unroll
            for (int mi = 0; mi < 4; mi++)
                #pragma unroll
                for (int nj = 0; nj < 4; nj++)
                    mma_bf16(acc[mi][nj], a_h[mi],
                             b_h[nj >> 1][(nj & 1) * 2], b_h[nj >> 1][(nj & 1) * 2 + 1]);
            #pragma unroll
            for (int np = 0; np < 2; np++)
                ldsm4t(b_l[np], bl4 + ks * 16 * B_STRIDE + np * 32);
            // group 2: hl — covers the a_l loads issued after
            #pragma unroll
            for (int mi = 0; mi < 4; mi++)
                #pragma unroll
                for (int nj = 0; nj < 4; nj++)
                    mma_bf16(acc[mi][nj], a_h[mi],
                             b_l[nj >> 1][(nj & 1) * 2], b_l[nj >> 1][(nj & 1) * 2 + 1]);
            #pragma unroll
            for (int mi = 0; mi < 4; mi++)
                ldsm4(a_l[mi], al4 + mi * 16 * A_STRIDE + ks * 32);
            // group 3: lh
            #pragma unroll
            for (int mi = 0; mi < 4; mi++)
                #pragma unroll
                for (int nj = 0; nj < 4; nj++)
                    mma_bf16(acc[mi][nj], a_l[mi],
                             b_h[nj >> 1][(nj & 1) * 2], b_h[nj >> 1][(nj & 1) * 2 + 1]);
        }
    };

    // R10 pipeline: issue at top, CP_WAIT(1), convert, sync, compute, sync
    issueF(0, 0); issueA(0, 0); CP_COMMIT();
    for (int kt = 0; kt < NKCH; kt++) {
        int buf = kt & 1;
        if (kt + 1 < NKCH) {
            issueF((kt + 1) * BK, buf ^ 1);
            issueA((kt + 1) * BK, buf ^ 1);
            CP_COMMIT();
            CP_WAIT(1);
        } else {
            CP_WAIT(0);
        }
        convertB(buf);
        __syncthreads();
        compute(buf);
        __syncthreads();
    }

    #pragma unroll
    for (int mi = 0; mi < 4; mi++) {
        int o0 = wo + mi * 16 + (lane >> 2);
        float b0 = __ldg(&bias[o0]);
        float b1 = __ldg(&bias[o0 + 8]);
        float* h0 = g_h + ((size_t)b * COUT + o0) * VRAW;
        float* h1 = h0 + (size_t)8 * VRAW;
        #pragma unroll
        for (int nj = 0; nj < 4; nj++) {
            int gv = v0 + wv + nj * 8 + (lane & 3) * 2;
            if (gv < VRAW) {
                *(float2*)(h0 + gv) = make_float2(acc[mi][nj][0] + b0,
                                                  acc[mi][nj][1] + b0);
                *(float2*)(h1 + gv) = make_float2(acc[mi][nj][2] + b1,
                                                  acc[mi][nj][3] + b1);
            }
        }
    }
}

// ---------------------------------------------------------------------------
// Kernel 3: persistent scatter (R10 version — measured 120us; frozen).
// ---------------------------------------------------------------------------
__global__ __launch_bounds__(1024, 1) void scatter_kernel(
    const int* __restrict__ mpi, float* __restrict__ y)
{
    extern __shared__ int win[];      // NVERT ints
    const int tid = threadIdx.x;

    // one-time zero (epoch starts at 1, so 0 never matches)
    {
        int4* w4 = (int4*)win;
        int4 z = make_int4(0, 0, 0, 0);
        #pragma unroll
        for (int i = 0; i < 10; i++) w4[tid + (i << 10)] = z;
        if (tid < 2) win[40960 + tid] = 0;
    }

    int row = blockIdx.x;
    int epoch = 1;
    int mk[11];
    {
        const int* mrow = mpi + (size_t)row * VRAW;
        #pragma unroll
        for (int i = 0; i < 11; i++) {
            int v = tid + (i << 10);
            mk[i] = (v < VRAW) ? __ldg(&mrow[v]) : 0;
        }
    }
    __syncthreads();

    while (row < NROWS) {
        const int tag = epoch << 14;
        // atomics phase
        #pragma unroll
        for (int i = 0; i < 11; i++) {
            int v = tid + (i << 10);
            if (v < VRAW) {
                int vert = g_nd[(v << 3) + mk[i]];
                atomicMax(&win[vert], tag | v);
            }
        }

        // prefetch next row's mpi (hides under write phase)
        int row2 = row + SC_GRID;
        int mk2[11];
        if (row2 < NROWS) {
            const int* mrow2 = mpi + (size_t)row2 * VRAW;
            #pragma unroll
            for (int i = 0; i < 11; i++) {
                int v = tid + (i << 10);
                mk2[i] = (v < VRAW) ? __ldg(&mrow2[v]) : 0;
            }
        }
        __syncthreads();   // atomics done before win reads

        // write phase: 10240 aligned float4 quads + one pair at the ragged end
        const float* hrow = g_h + (size_t)row * VRAW;
        float* yrow = y + (size_t)row * NVERT;
        const int s0 = (row & 1) ? 2 : 0;
        if (tid == 0) {
            int jp = (row & 1) ? 0 : 40960;
            int w0 = win[jp], w1 = win[jp + 1];
            float2 o;
            o.x = ((w0 >> 14) == epoch) ? __ldg(&hrow[w0 & 16383]) : 0.f;
            o.y = ((w1 >> 14) == epoch) ? __ldg(&hrow[w1 & 16383]) : 0.f;
            *(float2*)(yrow + jp) = o;
        }
        #pragma unroll
        for (int it = 0; it < 10; it++) {
            int q = tid + (it << 10);          // 0..10239
            int j = s0 + q * 4;
            int2 wa = *(const int2*)&win[j];
            int2 wb = *(const int2*)&win[j + 2];
            float4 o;
            o.x = ((wa.x >> 14) == epoch) ? __ldg(&hrow[wa.x & 16383]) : 0.f;
            o.y = ((wa.y >> 14) == epoch) ? __ldg(&hrow[wa.y & 16383]) : 0.f;
            o.z = ((wb.x >> 14) == epoch) ? __ldg(&hrow[wb.x & 16383]) : 0.f;
            o.w = ((wb.y >> 14) == epoch) ? __ldg(&hrow[wb.y & 16383]) : 0.f;
            *(float4*)(yrow + j) = o;
        }
        __syncthreads();   // win reads done before next row's atomics

        row = row2;
        epoch++;
        #pragma unroll
        for (int i = 0; i < 11; i++) mk[i] = mk2[i];
    }
}

// ---------------------------------------------------------------------------
extern "C" void kernel_launch(void* const* d_in, const int* in_sizes, int n_in,
                              void* d_out, int out_size)
{
    const float* x    = (const float*)d_in[0];
    const float* W    = (const float*)d_in[1];
    const float* bias = (const float*)d_in[2];
    const int*   up   = (const int*)d_in[3];
    const int*   down = (const int*)d_in[4];
    const int*   mpi  = (const int*)d_in[5];
    float* y = (float*)d_out;

    cudaFuncSetAttribute(scatter_kernel,
                         cudaFuncAttributeMaxDynamicSharedMemorySize, SC_SMEM);
    cudaFuncSetAttribute(gemm_mma_kernel,
                         cudaFuncAttributeMaxDynamicSharedMemorySize, SMEM_TOTAL);

    prep_kernel<<<PREP_W_BLOCKS + (VRAW * 8 + 255) / 256, 256>>>(W, up, down);

    dim3 g(NVB, NB);   // 81 x 16
    gemm_mma_kernel<<<g, 256, SMEM_TOTAL>>>(x, bias);

    scatter_kernel<<<SC_GRID, 1024, SC_SMEM>>>(mpi, y);
}

// round 14
// speedup vs baseline: 1.5342x; 1.0522x over previous
#include <cuda_runtime.h>
#include <cuda_bf16.h>
#include <cstdint>

#define NB    16
#define CIN   256
#define COUT  128
#define VRAW  10242
#define NVERT 40962
#define NROWS (NB * COUT)                 // 2048

#define BM    128
#define BNV   128
#define BK    32
#define NKCH  (CIN / BK)                  // 8
#define NVB   ((VRAW + BNV - 1) / BNV)    // 81

#define SC_GRID 148                       // persistent scatter CTAs (1/SM)

// Scratch (static __device__ — no allocation in kernel_launch)
__device__ float g_h[(size_t)NB * COUT * VRAW];   // 83.9 MB
__device__ int   g_nd[VRAW * 8];                  // 328 KB
__device__ __nv_bfloat16 g_Wh[COUT * CIN];
__device__ __nv_bfloat16 g_Wl[COUT * CIN];

// ---------------- gemm smem layout (bytes) — identical to R10 ----------------
#define A_STRIDE 80
#define B_STRIDE 272
#define F_STRIDE 528
#define A_TILE   (BM * A_STRIDE)
#define B_TILE   (BK * B_STRIDE)
#define F_TILE   (BK * F_STRIDE)
#define OFF_A    0
#define OFF_B    (4 * A_TILE)
#define OFF_F    (OFF_B + 4 * B_TILE)
#define SMEM_TOTAL (OFF_F + 2 * F_TILE)   // 109568 (2 CTAs/SM)

// ---------------- scatter smem: win[] only ----------------
#define SC_SMEM (NVERT * 4 + 8)           // 163856

// ---------------------------------------------------------------------------
__device__ __forceinline__ uint32_t smem_u32(const void* p) {
    uint32_t a;
    asm("{ .reg .u64 t; cvta.to.shared.u64 t, %1; cvt.u32.u64 %0, t; }"
        : "=r"(a) : "l"(p));
    return a;
}
__device__ __forceinline__ void cpa16(uint32_t dst, const void* src) {
    asm volatile("cp.async.cg.shared.global [%0], [%1], 16;"
                 :: "r"(dst), "l"(src) : "memory");
}
__device__ __forceinline__ void cpa8(uint32_t dst, const void* src) {
    asm volatile("cp.async.ca.shared.global [%0], [%1], 8;"
                 :: "r"(dst), "l"(src) : "memory");
}
__device__ __forceinline__ void cpa8z(uint32_t dst, const void* src, uint32_t bytes) {
    asm volatile("cp.async.ca.shared.global [%0], [%1], 8, %2;"
                 :: "r"(dst), "l"(src), "r"(bytes) : "memory");
}
#define CP_COMMIT() asm volatile("cp.async.commit_group;" ::: "memory")
#define CP_WAIT(N)  asm volatile("cp.async.wait_group %0;" :: "n"(N) : "memory")

__device__ __forceinline__ void ldsm4(uint32_t* r, uint32_t addr) {
    asm volatile("ldmatrix.sync.aligned.m8n8.x4.shared.b16 {%0,%1,%2,%3}, [%4];"
                 : "=r"(r[0]), "=r"(r[1]), "=r"(r[2]), "=r"(r[3]) : "r"(addr));
}
__device__ __forceinline__ void ldsm4t(uint32_t* r, uint32_t addr) {
    asm volatile("ldmatrix.sync.aligned.m8n8.x4.trans.shared.b16 {%0,%1,%2,%3}, [%4];"
                 : "=r"(r[0]), "=r"(r[1]), "=r"(r[2]), "=r"(r[3]) : "r"(addr));
}
__device__ __forceinline__ void mma_bf16(float* c, const uint32_t* a,
                                         uint32_t b0, uint32_t b1) {
    asm volatile(
        "mma.sync.aligned.m16n8k16.row.col.f32.bf16.bf16.f32 "
        "{%0,%1,%2,%3}, {%4,%5,%6,%7}, {%8,%9}, {%0,%1,%2,%3};"
        : "+f"(c[0]), "+f"(c[1]), "+f"(c[2]), "+f"(c[3])
        : "r"(a[0]), "r"(a[1]), "r"(a[2]), "r"(a[3]), "r"(b0), "r"(b1));
}

// ---- cheap two-term split
__device__ __forceinline__ uint32_t pack_hi(float a, float b) {
    uint32_t r;
    asm("prmt.b32 %0, %1, %2, 0x7632;"
        : "=r"(r) : "r"(__float_as_uint(a)), "r"(__float_as_uint(b)));
    return r;
}
__device__ __forceinline__ float hi_f(float a) {
    return __uint_as_float(__float_as_uint(a) & 0xFFFF0000u);
}
__device__ __forceinline__ uint32_t pack_lo(float a, float b) {
    float la = a - hi_f(a), lb = b - hi_f(b);
    uint32_t r;
    asm("cvt.rn.bf16x2.f32 %0, %1, %2;" : "=r"(r) : "f"(lb), "f"(la));
    return r;
}

// ---------------------------------------------------------------------------
// Kernel 0: merged prep — blocks [0,16): split W; blocks [16,337): nd table
// ---------------------------------------------------------------------------
#define PREP_W_BLOCKS 16
__global__ __launch_bounds__(256) void prep_kernel(const float* __restrict__ W,
                                                   const int* __restrict__ up,
                                                   const int* __restrict__ down)
{
    if (blockIdx.x < PREP_W_BLOCKS) {
        int t = blockIdx.x * 256 + threadIdx.x;
        if (t >= COUT * CIN / 8) return;
        const float4* src = (const float4*)W + t * 2;
        float4 f0 = src[0], f1 = src[1];
        uint4 hi, lo;
        hi.x = pack_hi(f0.x, f0.y); lo.x = pack_lo(f0.x, f0.y);
        hi.y = pack_hi(f0.z, f0.w); lo.y = pack_lo(f0.z, f0.w);
        hi.z = pack_hi(f1.x, f1.y); lo.z = pack_lo(f1.x, f1.y);
        hi.w = pack_hi(f1.z, f1.w); lo.w = pack_lo(f1.z, f1.w);
        *(uint4*)(g_Wh + t * 8) = hi;
        *(uint4*)(g_Wl + t * 8) = lo;
    } else {
        int i = (blockIdx.x - PREP_W_BLOCKS) * 256 + threadIdx.x;
        if (i >= VRAW * 8) return;
        int v = i >> 3, k = i & 7;
        int val = 0;
        if (k < 7) val = up[down[v] * 7 + k];
        g_nd[i] = val;
    }
}

// ---------------------------------------------------------------------------
// Kernel 2: HMMA GEMM — R10 pipeline, but 512 threads / 16 warps,
// warp tile 32x32 (acc=32 regs) -> 2 CTAs/SM at 50% occupancy.
// All smem layouts and per-warp ldmatrix addressing identical to R10.
// ---------------------------------------------------------------------------
__global__ __launch_bounds__(512, 2)
void gemm_mma_kernel(const float* __restrict__ x, const float* __restrict__ bias)
{
    extern __shared__ char smem[];
    const uint32_t sbase = smem_u32(smem);
    const int tid  = threadIdx.x;
    const int lane = tid & 31;
    const int wid  = tid >> 5;            // 0..15
    const int b    = blockIdx.y;
    const int v0   = blockIdx.x * BNV;
    const int wo   = (wid >> 2) * 32;     // warp o-base: 0/32/64/96
    const int wv   = (wid & 3) * 32;      // warp v-base: 0/32/64/96
    const bool fullv = (v0 + BNV) <= VRAW;

    float acc[2][4][4];
    #pragma unroll
    for (int i = 0; i < 2; i++)
        #pragma unroll
        for (int j = 0; j < 4; j++)
            #pragma unroll
            for (int e = 0; e < 4; e++) acc[i][j][e] = 0.f;

    // A (pre-split W): 1+1 cpa16 per thread (512 threads cover 128x32 hi+lo)
    auto issueA = [&](int kc, int buf) {
        int o = tid >> 2, q = tid & 3;
        const __nv_bfloat16* sh = g_Wh + o * CIN + kc + q * 8;
        const __nv_bfloat16* sl = g_Wl + o * CIN + kc + q * 8;
        uint32_t dh = sbase + OFF_A + (buf * 2 + 0) * A_TILE + o * A_STRIDE + q * 16;
        cpa16(dh, sh);
        cpa16(dh + A_TILE, sl);
    };
    // B fp32 staging: 4 cpa8 per thread (c = tid>>4, seg of 8 floats)
    auto issueF = [&](int kc, int fb) {
        int c = tid >> 4, seg = tid & 15;
        const float* src = x + ((size_t)(b * CIN + kc + c)) * VRAW + v0 + seg * 8;
        uint32_t dst = sbase + OFF_F + fb * F_TILE + c * F_STRIDE + seg * 32;
        if (fullv) {
            #pragma unroll
            for (int j = 0; j < 4; j++) cpa8(dst + j * 8, src + j * 2);
        } else {
            #pragma unroll
            for (int j = 0; j < 4; j++) {
                int gv = v0 + seg * 8 + j * 2;
                uint32_t bytes = (gv + 2 <= VRAW) ? 8u : 0u;
                cpa8z(dst + j * 8, bytes ? (src + j * 2) : x, bytes);
            }
        }
    };
    // convert own 8 floats -> 8 bf16 hi + 8 bf16 lo
    auto convertB = [&](int buf) {
        int c = tid >> 4, seg = tid & 15;
        const char* fp = smem + OFF_F + (buf & 1) * F_TILE + c * F_STRIDE + seg * 32;
        float4 q0 = *(const float4*)(fp);
        float4 q1 = *(const float4*)(fp + 16);
        uint4 hi, lo;
        hi.x = pack_hi(q0.x, q0.y); lo.x = pack_lo(q0.x, q0.y);
        hi.y = pack_hi(q0.z, q0.w); lo.y = pack_lo(q0.z, q0.w);
        hi.z = pack_hi(q1.x, q1.y); lo.z = pack_lo(q1.x, q1.y);
        hi.w = pack_hi(q1.z, q1.w); lo.w = pack_lo(q1.z, q1.w);
        char* bh = smem + OFF_B + (buf * 2 + 0) * B_TILE + c * B_STRIDE + seg * 16;
        *(uint4*)(bh)          = hi;
        *(uint4*)(bh + B_TILE) = lo;
    };

    const int arow   = lane & 15;
    const int acol16 = (lane >> 4) * 16;
    const int brow   = ((lane >> 3) & 1) * 8 + (lane & 7);
    const int bcol16 = (lane >> 4) * 16;

    auto compute = [&](int buf) {
        uint32_t ah4 = sbase + OFF_A + (buf * 2) * A_TILE + (wo + arow) * A_STRIDE + acol16;
        uint32_t al4 = ah4 + A_TILE;
        uint32_t bh4 = sbase + OFF_B + (buf * 2) * B_TILE + brow * B_STRIDE + wv * 2 + bcol16;
        uint32_t bl4 = bh4 + B_TILE;
        #pragma unroll
        for (int ks = 0; ks < 2; ks++) {
            uint32_t a_h[2][4], a_l[2][4], b_h[2][4], b_l[2][4];
            #pragma unroll
            for (int mi = 0; mi < 2; mi++)
                ldsm4(a_h[mi], ah4 + mi * 16 * A_STRIDE + ks * 32);
            #pragma unroll
            for (int np = 0; np < 2; np++)
                ldsm4t(b_h[np], bh4 + ks * 16 * B_STRIDE + np * 32);
            // group 1: hh
            #pragma unroll
            for (int mi = 0; mi < 2; mi++)
                #pragma unroll
                for (int nj = 0; nj < 4; nj++)
                    mma_bf16(acc[mi][nj], a_h[mi],
                             b_h[nj >> 1][(nj & 1) * 2], b_h[nj >> 1][(nj & 1) * 2 + 1]);
            #pragma unroll
            for (int np = 0; np < 2; np++)
                ldsm4t(b_l[np], bl4 + ks * 16 * B_STRIDE + np * 32);
            // group 2: hl
            #pragma unroll
            for (int mi = 0; mi < 2; mi++)
                #pragma unroll
                for (int nj = 0; nj < 4; nj++)
                    mma_bf16(acc[mi][nj], a_h[mi],
                             b_l[nj >> 1][(nj & 1) * 2], b_l[nj >> 1][(nj & 1) * 2 + 1]);
            #pragma unroll
            for (int mi = 0; mi < 2; mi++)
                ldsm4(a_l[mi], al4 + mi * 16 * A_STRIDE + ks * 32);
            // group 3: lh
            #pragma unroll
            for (int mi = 0; mi < 2; mi++)
                #pragma unroll
                for (int nj = 0; nj < 4; nj++)
                    mma_bf16(acc[mi][nj], a_l[mi],
                             b_h[nj >> 1][(nj & 1) * 2], b_h[nj >> 1][(nj & 1) * 2 + 1]);
        }
    };

    // R10 pipeline: issue at top, CP_WAIT(1), convert, sync, compute, sync
    issueF(0, 0); issueA(0, 0); CP_COMMIT();
    for (int kt = 0; kt < NKCH; kt++) {
        int buf = kt & 1;
        if (kt + 1 < NKCH) {
            issueF((kt + 1) * BK, buf ^ 1);
            issueA((kt + 1) * BK, buf ^ 1);
            CP_COMMIT();
            CP_WAIT(1);
        } else {
            CP_WAIT(0);
        }
        convertB(buf);
        __syncthreads();
        compute(buf);
        __syncthreads();
    }

    // epilogue: acc + bias -> g_h
    #pragma unroll
    for (int mi = 0; mi < 2; mi++) {
        int o0 = wo + mi * 16 + (lane >> 2);
        float b0 = __ldg(&bias[o0]);
        float b1 = __ldg(&bias[o0 + 8]);
        float* h0 = g_h + ((size_t)b * COUT + o0) * VRAW;
        float* h1 = h0 + (size_t)8 * VRAW;
        #pragma unroll
        for (int nj = 0; nj < 4; nj++) {
            int gv = v0 + wv + nj * 8 + (lane & 3) * 2;
            if (gv < VRAW) {
                *(float2*)(h0 + gv) = make_float2(acc[mi][nj][0] + b0,
                                                  acc[mi][nj][1] + b0);
                *(float2*)(h1 + gv) = make_float2(acc[mi][nj][2] + b1,
                                                  acc[mi][nj][3] + b1);
            }
        }
    }
}

// ---------------------------------------------------------------------------
// Kernel 3: persistent scatter (R10 version — measured 120us; frozen).
// ---------------------------------------------------------------------------
__global__ __launch_bounds__(1024, 1) void scatter_kernel(
    const int* __restrict__ mpi, float* __restrict__ y)
{
    extern __shared__ int win[];      // NVERT ints
    const int tid = threadIdx.x;

    // one-time zero (epoch starts at 1, so 0 never matches)
    {
        int4* w4 = (int4*)win;
        int4 z = make_int4(0, 0, 0, 0);
        #pragma unroll
        for (int i = 0; i < 10; i++) w4[tid + (i << 10)] = z;
        if (tid < 2) win[40960 + tid] = 0;
    }

    int row = blockIdx.x;
    int epoch = 1;
    int mk[11];
    {
        const int* mrow = mpi + (size_t)row * VRAW;
        #pragma unroll
        for (int i = 0; i < 11; i++) {
            int v = tid + (i << 10);
            mk[i] = (v < VRAW) ? __ldg(&mrow[v]) : 0;
        }
    }
    __syncthreads();

    while (row < NROWS) {
        const int tag = epoch << 14;
        // atomics phase
        #pragma unroll
        for (int i = 0; i < 11; i++) {
            int v = tid + (i << 10);
            if (v < VRAW) {
                int vert = g_nd[(v << 3) + mk[i]];
                atomicMax(&win[vert], tag | v);
            }
        }

        // prefetch next row's mpi (hides under write phase)
        int row2 = row + SC_GRID;
        int mk2[11];
        if (row2 < NROWS) {
            const int* mrow2 = mpi + (size_t)row2 * VRAW;
            #pragma unroll
            for (int i = 0; i < 11; i++) {
                int v = tid + (i << 10);
                mk2[i] = (v < VRAW) ? __ldg(&mrow2[v]) : 0;
            }
        }
        __syncthreads();   // atomics done before win reads

        // write phase: 10240 aligned float4 quads + one pair at the ragged end
        const float* hrow = g_h + (size_t)row * VRAW;
        float* yrow = y + (size_t)row * NVERT;
        const int s0 = (row & 1) ? 2 : 0;
        if (tid == 0) {
            int jp = (row & 1) ? 0 : 40960;
            int w0 = win[jp], w1 = win[jp + 1];
            float2 o;
            o.x = ((w0 >> 14) == epoch) ? __ldg(&hrow[w0 & 16383]) : 0.f;
            o.y = ((w1 >> 14) == epoch) ? __ldg(&hrow[w1 & 16383]) : 0.f;
            *(float2*)(yrow + jp) = o;
        }
        #pragma unroll
        for (int it = 0; it < 10; it++) {
            int q = tid + (it << 10);          // 0..10239
            int j = s0 + q * 4;
            int2 wa = *(const int2*)&win[j];
            int2 wb = *(const int2*)&win[j + 2];
            float4 o;
            o.x = ((wa.x >> 14) == epoch) ? __ldg(&hrow[wa.x & 16383]) : 0.f;
            o.y = ((wa.y >> 14) == epoch) ? __ldg(&hrow[wa.y & 16383]) : 0.f;
            o.z = ((wb.x >> 14) == epoch) ? __ldg(&hrow[wb.x & 16383]) : 0.f;
            o.w = ((wb.y >> 14) == epoch) ? __ldg(&hrow[wb.y & 16383]) : 0.f;
            *(float4*)(yrow + j) = o;
        }
        __syncthreads();   // win reads done before next row's atomics

        row = row2;
        epoch++;
        #pragma unroll
        for (int i = 0; i < 11; i++) mk[i] = mk2[i];
    }
}

// ---------------------------------------------------------------------------
extern "C" void kernel_launch(void* const* d_in, const int* in_sizes, int n_in,
                              void* d_out, int out_size)
{
    const float* x    = (const float*)d_in[0];
    const float* W    = (const float*)d_in[1];
    const float* bias = (const float*)d_in[2];
    const int*   up   = (const int*)d_in[3];
    const int*   down = (const int*)d_in[4];
    const int*   mpi  = (const int*)d_in[5];
    float* y = (float*)d_out;

    cudaFuncSetAttribute(scatter_kernel,
                         cudaFuncAttributeMaxDynamicSharedMemorySize, SC_SMEM);
    cudaFuncSetAttribute(gemm_mma_kernel,
                         cudaFuncAttributeMaxDynamicSharedMemorySize, SMEM_TOTAL);

    prep_kernel<<<PREP_W_BLOCKS + (VRAW * 8 + 255) / 256, 256>>>(W, up, down);

    dim3 g(NVB, NB);   // 81 x 16
    gemm_mma_kernel<<<g, 512, SMEM_TOTAL>>>(x, bias);

    scatter_kernel<<<SC_GRID, 1024, SC_SMEM>>>(mpi, y);
}

// round 16
// speedup vs baseline: 1.5992x; 1.0424x over previous
#include <cuda_runtime.h>
#include <cuda_bf16.h>
#include <cstdint>

#define NB    16
#define CIN   256
#define COUT  128
#define VRAW  10242
#define NVERT 40962
#define NROWS (NB * COUT)                 // 2048

#define BM    128
#define BNV   128
#define BK    32
#define NKCH  (CIN / BK)                  // 8
#define NVB   ((VRAW + BNV - 1) / BNV)    // 81

#define SC_GRID 148                       // persistent scatter CTAs (1/SM)

// Scratch (static __device__ — no allocation in kernel_launch)
__device__ float g_h[(size_t)NB * COUT * VRAW];   // 83.9 MB
__device__ unsigned short g_nd16[VRAW * 8];       // 164 KB (u16 verts)
__device__ __nv_bfloat16 g_Wh[COUT * CIN];
__device__ __nv_bfloat16 g_Wl[COUT * CIN];

// ---------------- gemm smem layout (bytes) — identical to R14 ----------------
#define A_STRIDE 80
#define B_STRIDE 272
#define F_STRIDE 528
#define A_TILE   (BM * A_STRIDE)
#define B_TILE   (BK * B_STRIDE)
#define F_TILE   (BK * F_STRIDE)
#define OFF_A    0
#define OFF_B    (4 * A_TILE)
#define OFF_F    (OFF_B + 4 * B_TILE)
#define SMEM_TOTAL (OFF_F + 2 * F_TILE)   // 109568 (2 CTAs/SM)

// ---------------- scatter smem: win[] only ----------------
#define SC_SMEM (NVERT * 4 + 8)           // 163856

// ---------------------------------------------------------------------------
__device__ __forceinline__ uint32_t smem_u32(const void* p) {
    uint32_t a;
    asm("{ .reg .u64 t; cvta.to.shared.u64 t, %1; cvt.u32.u64 %0, t; }"
        : "=r"(a) : "l"(p));
    return a;
}
__device__ __forceinline__ void cpa16(uint32_t dst, const void* src) {
    asm volatile("cp.async.cg.shared.global [%0], [%1], 16;"
                 :: "r"(dst), "l"(src) : "memory");
}
__device__ __forceinline__ void cpa8(uint32_t dst, const void* src) {
    asm volatile("cp.async.ca.shared.global [%0], [%1], 8;"
                 :: "r"(dst), "l"(src) : "memory");
}
__device__ __forceinline__ void cpa8z(uint32_t dst, const void* src, uint32_t bytes) {
    asm volatile("cp.async.ca.shared.global [%0], [%1], 8, %2;"
                 :: "r"(dst), "l"(src), "r"(bytes) : "memory");
}
#define CP_COMMIT() asm volatile("cp.async.commit_group;" ::: "memory")
#define CP_WAIT(N)  asm volatile("cp.async.wait_group %0;" :: "n"(N) : "memory")

__device__ __forceinline__ void ldsm4(uint32_t* r, uint32_t addr) {
    asm volatile("ldmatrix.sync.aligned.m8n8.x4.shared.b16 {%0,%1,%2,%3}, [%4];"
                 : "=r"(r[0]), "=r"(r[1]), "=r"(r[2]), "=r"(r[3]) : "r"(addr));
}
__device__ __forceinline__ void ldsm4t(uint32_t* r, uint32_t addr) {
    asm volatile("ldmatrix.sync.aligned.m8n8.x4.trans.shared.b16 {%0,%1,%2,%3}, [%4];"
                 : "=r"(r[0]), "=r"(r[1]), "=r"(r[2]), "=r"(r[3]) : "r"(addr));
}
__device__ __forceinline__ void mma_bf16(float* c, const uint32_t* a,
                                         uint32_t b0, uint32_t b1) {
    asm volatile(
        "mma.sync.aligned.m16n8k16.row.col.f32.bf16.bf16.f32 "
        "{%0,%1,%2,%3}, {%4,%5,%6,%7}, {%8,%9}, {%0,%1,%2,%3};"
        : "+f"(c[0]), "+f"(c[1]), "+f"(c[2]), "+f"(c[3])
        : "r"(a[0]), "r"(a[1]), "r"(a[2]), "r"(a[3]), "r"(b0), "r"(b1));
}

// ---- cheap two-term split
__device__ __forceinline__ uint32_t pack_hi(float a, float b) {
    uint32_t r;
    asm("prmt.b32 %0, %1, %2, 0x7632;"
        : "=r"(r) : "r"(__float_as_uint(a)), "r"(__float_as_uint(b)));
    return r;
}
__device__ __forceinline__ float hi_f(float a) {
    return __uint_as_float(__float_as_uint(a) & 0xFFFF0000u);
}
__device__ __forceinline__ uint32_t pack_lo(float a, float b) {
    float la = a - hi_f(a), lb = b - hi_f(b);
    uint32_t r;
    asm("cvt.rn.bf16x2.f32 %0, %1, %2;" : "=r"(r) : "f"(lb), "f"(la));
    return r;
}

// ---------------------------------------------------------------------------
// Kernel 0: merged prep — blocks [0,16): split W; blocks [16,337): nd table
// ---------------------------------------------------------------------------
#define PREP_W_BLOCKS 16
__global__ __launch_bounds__(256) void prep_kernel(const float* __restrict__ W,
                                                   const int* __restrict__ up,
                                                   const int* __restrict__ down)
{
    if (blockIdx.x < PREP_W_BLOCKS) {
        int t = blockIdx.x * 256 + threadIdx.x;
        if (t >= COUT * CIN / 8) return;
        const float4* src = (const float4*)W + t * 2;
        float4 f0 = src[0], f1 = src[1];
        uint4 hi, lo;
        hi.x = pack_hi(f0.x, f0.y); lo.x = pack_lo(f0.x, f0.y);
        hi.y = pack_hi(f0.z, f0.w); lo.y = pack_lo(f0.z, f0.w);
        hi.z = pack_hi(f1.x, f1.y); lo.z = pack_lo(f1.x, f1.y);
        hi.w = pack_hi(f1.z, f1.w); lo.w = pack_lo(f1.z, f1.w);
        *(uint4*)(g_Wh + t * 8) = hi;
        *(uint4*)(g_Wl + t * 8) = lo;
    } else {
        int i = (blockIdx.x - PREP_W_BLOCKS) * 256 + threadIdx.x;
        if (i >= VRAW * 8) return;
        int v = i >> 3, k = i & 7;
        int val = 0;
        if (k < 7) val = up[down[v] * 7 + k];
        g_nd16[i] = (unsigned short)val;
    }
}

// ---------------------------------------------------------------------------
// Kernel 2: HMMA GEMM (identical to R14 — 512 thr / 16 warps, 2 CTAs/SM).
// ---------------------------------------------------------------------------
__global__ __launch_bounds__(512, 2)
void gemm_mma_kernel(const float* __restrict__ x, const float* __restrict__ bias)
{
    extern __shared__ char smem[];
    const uint32_t sbase = smem_u32(smem);
    const int tid  = threadIdx.x;
    const int lane = tid & 31;
    const int wid  = tid >> 5;            // 0..15
    const int b    = blockIdx.y;
    const int v0   = blockIdx.x * BNV;
    const int wo   = (wid >> 2) * 32;
    const int wv   = (wid & 3) * 32;
    const bool fullv = (v0 + BNV) <= VRAW;

    float acc[2][4][4];
    #pragma unroll
    for (int i = 0; i < 2; i++)
        #pragma unroll
        for (int j = 0; j < 4; j++)
            #pragma unroll
            for (int e = 0; e < 4; e++) acc[i][j][e] = 0.f;

    auto issueA = [&](int kc, int buf) {
        int o = tid >> 2, q = tid & 3;
        const __nv_bfloat16* sh = g_Wh + o * CIN + kc + q * 8;
        const __nv_bfloat16* sl = g_Wl + o * CIN + kc + q * 8;
        uint32_t dh = sbase + OFF_A + (buf * 2 + 0) * A_TILE + o * A_STRIDE + q * 16;
        cpa16(dh, sh);
        cpa16(dh + A_TILE, sl);
    };
    auto issueF = [&](int kc, int fb) {
        int c = tid >> 4, seg = tid & 15;
        const float* src = x + ((size_t)(b * CIN + kc + c)) * VRAW + v0 + seg * 8;
        uint32_t dst = sbase + OFF_F + fb * F_TILE + c * F_STRIDE + seg * 32;
        if (fullv) {
            #pragma unroll
            for (int j = 0; j < 4; j++) cpa8(dst + j * 8, src + j * 2);
        } else {
            #pragma unroll
            for (int j = 0; j < 4; j++) {
                int gv = v0 + seg * 8 + j * 2;
                uint32_t bytes = (gv + 2 <= VRAW) ? 8u : 0u;
                cpa8z(dst + j * 8, bytes ? (src + j * 2) : x, bytes);
            }
        }
    };
    auto convertB = [&](int buf) {
        int c = tid >> 4, seg = tid & 15;
        const char* fp = smem + OFF_F + (buf & 1) * F_TILE + c * F_STRIDE + seg * 32;
        float4 q0 = *(const float4*)(fp);
        float4 q1 = *(const float4*)(fp + 16);
        uint4 hi, lo;
        hi.x = pack_hi(q0.x, q0.y); lo.x = pack_lo(q0.x, q0.y);
        hi.y = pack_hi(q0.z, q0.w); lo.y = pack_lo(q0.z, q0.w);
        hi.z = pack_hi(q1.x, q1.y); lo.z = pack_lo(q1.x, q1.y);
        hi.w = pack_hi(q1.z, q1.w); lo.w = pack_lo(q1.z, q1.w);
        char* bh = smem + OFF_B + (buf * 2 + 0) * B_TILE + c * B_STRIDE + seg * 16;
        *(uint4*)(bh)          = hi;
        *(uint4*)(bh + B_TILE) = lo;
    };

    const int arow   = lane & 15;
    const int acol16 = (lane >> 4) * 16;
    const int brow   = ((lane >> 3) & 1) * 8 + (lane & 7);
    const int bcol16 = (lane >> 4) * 16;

    auto compute = [&](int buf) {
        uint32_t ah4 = sbase + OFF_A + (buf * 2) * A_TILE + (wo + arow) * A_STRIDE + acol16;
        uint32_t al4 = ah4 + A_TILE;
        uint32_t bh4 = sbase + OFF_B + (buf * 2) * B_TILE + brow * B_STRIDE + wv * 2 + bcol16;
        uint32_t bl4 = bh4 + B_TILE;
        #pragma unroll
        for (int ks = 0; ks < 2; ks++) {
            uint32_t a_h[2][4], a_l[2][4], b_h[2][4], b_l[2][4];
            #pragma unroll
            for (int mi = 0; mi < 2; mi++)
                ldsm4(a_h[mi], ah4 + mi * 16 * A_STRIDE + ks * 32);
            #pragma unroll
            for (int np = 0; np < 2; np++)
                ldsm4t(b_h[np], bh4 + ks * 16 * B_STRIDE + np * 32);
            #pragma unroll
            for (int mi = 0; mi < 2; mi++)
                #pragma unroll
                for (int nj = 0; nj < 4; nj++)
                    mma_bf16(acc[mi][nj], a_h[mi],
                             b_h[nj >> 1][(nj & 1) * 2], b_h[nj >> 1][(nj & 1) * 2 + 1]);
            #pragma unroll
            for (int np = 0; np < 2; np++)
                ldsm4t(b_l[np], bl4 + ks * 16 * B_STRIDE + np * 32);
            #pragma unroll
            for (int mi = 0; mi < 2; mi++)
                #pragma unroll
                for (int nj = 0; nj < 4; nj++)
                    mma_bf16(acc[mi][nj], a_h[mi],
                             b_l[nj >> 1][(nj & 1) * 2], b_l[nj >> 1][(nj & 1) * 2 + 1]);
            #pragma unroll
            for (int mi = 0; mi < 2; mi++)
                ldsm4(a_l[mi], al4 + mi * 16 * A_STRIDE + ks * 32);
            #pragma unroll
            for (int mi = 0; mi < 2; mi++)
                #pragma unroll
                for (int nj = 0; nj < 4; nj++)
                    mma_bf16(acc[mi][nj], a_l[mi],
                             b_h[nj >> 1][(nj & 1) * 2], b_h[nj >> 1][(nj & 1) * 2 + 1]);
        }
    };

    issueF(0, 0); issueA(0, 0); CP_COMMIT();
    for (int kt = 0; kt < NKCH; kt++) {
        int buf = kt & 1;
        if (kt + 1 < NKCH) {
            issueF((kt + 1) * BK, buf ^ 1);
            issueA((kt + 1) * BK, buf ^ 1);
            CP_COMMIT();
            CP_WAIT(1);
        } else {
            CP_WAIT(0);
        }
        convertB(buf);
        __syncthreads();
        compute(buf);
        __syncthreads();
    }

    #pragma unroll
    for (int mi = 0; mi < 2; mi++) {
        int o0 = wo + mi * 16 + (lane >> 2);
        float b0 = __ldg(&bias[o0]);
        float b1 = __ldg(&bias[o0 + 8]);
        float* h0 = g_h + ((size_t)b * COUT + o0) * VRAW;
        float* h1 = h0 + (size_t)8 * VRAW;
        #pragma unroll
        for (int nj = 0; nj < 4; nj++) {
            int gv = v0 + wv + nj * 8 + (lane & 3) * 2;
            if (gv < VRAW) {
                *(float2*)(h0 + gv) = make_float2(acc[mi][nj][0] + b0,
                                                  acc[mi][nj][1] + b0);
                *(float2*)(h1 + gv) = make_float2(acc[mi][nj][2] + b1,
                                                  acc[mi][nj][3] + b1);
            }
        }
    }
}

// ---------------------------------------------------------------------------
// Kernel 3: persistent scatter. Atomic phase = pure smem atomicMax: the
// nd-gather for row N+1 is resolved during row N's write phase (latency and
// wavefronts hidden under the LSU-bound write loop), using the u16 nd table.
// ---------------------------------------------------------------------------
__global__ __launch_bounds__(1024, 1) void scatter_kernel(
    const int* __restrict__ mpi, float* __restrict__ y)
{
    extern __shared__ int win[];      // NVERT ints
    const int tid = threadIdx.x;

    // one-time zero (epoch starts at 1, so 0 never matches)
    {
        int4* w4 = (int4*)win;
        int4 z = make_int4(0, 0, 0, 0);
        #pragma unroll
        for (int i = 0; i < 10; i++) w4[tid + (i << 10)] = z;
        if (tid < 2) win[40960 + tid] = 0;
    }

    int row = blockIdx.x;
    int epoch = 1;
    int vert[11];
    {   // startup: resolve first row's verts (exposed once)
        const int* mrow = mpi + (size_t)row * VRAW;
        int mk[11];
        #pragma unroll
        for (int i = 0; i < 11; i++) {
            int v = tid + (i << 10);
            mk[i] = (v < VRAW) ? __ldg(&mrow[v]) : 0;
        }
        #pragma unroll
        for (int i = 0; i < 11; i++) {
            int v = tid + (i << 10);
            vert[i] = (v < VRAW) ? (int)__ldg(&g_nd16[(v << 3) + mk[i]]) : 0;
        }
    }
    __syncthreads();

    while (row < NROWS) {
        const int tag = epoch << 14;
        // atomic phase: pure shared atomicMax
        #pragma unroll
        for (int i = 0; i < 11; i++) {
            int v = tid + (i << 10);
            if (v < VRAW) atomicMax(&win[vert[i]], tag | v);
        }

        // prefetch next row's mpi (LDGs fly over the barrier + write phase)
        int row2 = row + SC_GRID;
        int mk2[11];
        if (row2 < NROWS) {
            const int* mrow2 = mpi + (size_t)row2 * VRAW;
            #pragma unroll
            for (int i = 0; i < 11; i++) {
                int v = tid + (i << 10);
                mk2[i] = (v < VRAW) ? __ldg(&mrow2[v]) : 0;
            }
        }
        __syncthreads();   // atomics done before win reads

        // resolve next row's verts now — latency hides under the write loop
        if (row2 < NROWS) {
            #pragma unroll
            for (int i = 0; i < 11; i++) {
                int v = tid + (i << 10);
                vert[i] = (v < VRAW) ? (int)__ldg(&g_nd16[(v << 3) + mk2[i]]) : 0;
            }
        }

        // write phase: 10240 aligned float4 quads + one pair at the ragged end
        const float* hrow = g_h + (size_t)row * VRAW;
        float* yrow = y + (size_t)row * NVERT;
        const int s0 = (row & 1) ? 2 : 0;
        if (tid == 0) {
            int jp = (row & 1) ? 0 : 40960;
            int w0 = win[jp], w1 = win[jp + 1];
            float2 o;
            o.x = ((w0 >> 14) == epoch) ? __ldg(&hrow[w0 & 16383]) : 0.f;
            o.y = ((w1 >> 14) == epoch) ? __ldg(&hrow[w1 & 16383]) : 0.f;
            *(float2*)(yrow + jp) = o;
        }
        #pragma unroll
        for (int it = 0; it < 10; it++) {
            int q = tid + (it << 10);          // 0..10239
            int j = s0 + q * 4;
            int2 wa = *(const int2*)&win[j];
            int2 wb = *(const int2*)&win[j + 2];
            float4 o;
            o.x = ((wa.x >> 14) == epoch) ? __ldg(&hrow[wa.x & 16383]) : 0.f;
            o.y = ((wa.y >> 14) == epoch) ? __ldg(&hrow[wa.y & 16383]) : 0.f;
            o.z = ((wb.x >> 14) == epoch) ? __ldg(&hrow[wb.x & 16383]) : 0.f;
            o.w = ((wb.y >> 14) == epoch) ? __ldg(&hrow[wb.y & 16383]) : 0.f;
            *(float4*)(yrow + j) = o;
        }
        __syncthreads();   // win reads done before next row's atomics

        row = row2;
        epoch++;
    }
}

// ---------------------------------------------------------------------------
extern "C" void kernel_launch(void* const* d_in, const int* in_sizes, int n_in,
                              void* d_out, int out_size)
{
    const float* x    = (const float*)d_in[0];
    const float* W    = (const float*)d_in[1];
    const float* bias = (const float*)d_in[2];
    const int*   up   = (const int*)d_in[3];
    const int*   down = (const int*)d_in[4];
    const int*   mpi  = (const int*)d_in[5];
    float* y = (float*)d_out;

    cudaFuncSetAttribute(scatter_kernel,
                         cudaFuncAttributeMaxDynamicSharedMemorySize, SC_SMEM);
    cudaFuncSetAttribute(gemm_mma_kernel,
                         cudaFuncAttributeMaxDynamicSharedMemorySize, SMEM_TOTAL);

    prep_kernel<<<PREP_W_BLOCKS + (VRAW * 8 + 255) / 256, 256>>>(W, up, down);

    dim3 g(NVB, NB);   // 81 x 16
    gemm_mma_kernel<<<g, 512, SMEM_TOTAL>>>(x, bias);

    scatter_kernel<<<SC_GRID, 1024, SC_SMEM>>>(mpi, y);
}

// round 17
// speedup vs baseline: 1.6046x; 1.0033x over previous
#include <cuda_runtime.h>
#include <cuda_bf16.h>
#include <cstdint>

#define NB    16
#define CIN   256
#define COUT  128
#define VRAW  10242
#define NVERT 40962
#define NROWS (NB * COUT)                 // 2048

#define BM    128
#define BNV   128
#define BK    32
#define NKCH  (CIN / BK)                  // 8
#define NVB   ((VRAW + BNV - 1) / BNV)    // 81

#define SC_GRID 148                       // persistent scatter CTAs (1/SM)

// Scratch (static __device__ — no allocation in kernel_launch)
__device__ float g_h[(size_t)NB * COUT * VRAW];   // 83.9 MB
__device__ unsigned short g_nd16[VRAW * 8];       // 164 KB (u16 verts)
__device__ __nv_bfloat16 g_Wh[COUT * CIN];
__device__ __nv_bfloat16 g_Wl[COUT * CIN];

// ---------------- gemm smem layout (bytes) — identical to R14 ----------------
#define A_STRIDE 80
#define B_STRIDE 272
#define F_STRIDE 528
#define A_TILE   (BM * A_STRIDE)
#define B_TILE   (BK * B_STRIDE)
#define F_TILE   (BK * F_STRIDE)
#define OFF_A    0
#define OFF_B    (4 * A_TILE)
#define OFF_F    (OFF_B + 4 * B_TILE)
#define SMEM_TOTAL (OFF_F + 2 * F_TILE)   // 109568 (2 CTAs/SM)

// ---------------- scatter smem: win[] only ----------------
#define SC_SMEM (NVERT * 4 + 8)           // 163856

// ---------------------------------------------------------------------------
__device__ __forceinline__ uint32_t smem_u32(const void* p) {
    uint32_t a;
    asm("{ .reg .u64 t; cvta.to.shared.u64 t, %1; cvt.u32.u64 %0, t; }"
        : "=r"(a) : "l"(p));
    return a;
}
__device__ __forceinline__ void cpa16(uint32_t dst, const void* src) {
    asm volatile("cp.async.cg.shared.global [%0], [%1], 16;"
                 :: "r"(dst), "l"(src) : "memory");
}
__device__ __forceinline__ void cpa8(uint32_t dst, const void* src) {
    asm volatile("cp.async.ca.shared.global [%0], [%1], 8;"
                 :: "r"(dst), "l"(src) : "memory");
}
__device__ __forceinline__ void cpa8z(uint32_t dst, const void* src, uint32_t bytes) {
    asm volatile("cp.async.ca.shared.global [%0], [%1], 8, %2;"
                 :: "r"(dst), "l"(src), "r"(bytes) : "memory");
}
#define CP_COMMIT() asm volatile("cp.async.commit_group;" ::: "memory")
#define CP_WAIT(N)  asm volatile("cp.async.wait_group %0;" :: "n"(N) : "memory")

__device__ __forceinline__ void ldsm4(uint32_t* r, uint32_t addr) {
    asm volatile("ldmatrix.sync.aligned.m8n8.x4.shared.b16 {%0,%1,%2,%3}, [%4];"
                 : "=r"(r[0]), "=r"(r[1]), "=r"(r[2]), "=r"(r[3]) : "r"(addr));
}
__device__ __forceinline__ void ldsm4t(uint32_t* r, uint32_t addr) {
    asm volatile("ldmatrix.sync.aligned.m8n8.x4.trans.shared.b16 {%0,%1,%2,%3}, [%4];"
                 : "=r"(r[0]), "=r"(r[1]), "=r"(r[2]), "=r"(r[3]) : "r"(addr));
}
__device__ __forceinline__ void mma_bf16(float* c, const uint32_t* a,
                                         uint32_t b0, uint32_t b1) {
    asm volatile(
        "mma.sync.aligned.m16n8k16.row.col.f32.bf16.bf16.f32 "
        "{%0,%1,%2,%3}, {%4,%5,%6,%7}, {%8,%9}, {%0,%1,%2,%3};"
        : "+f"(c[0]), "+f"(c[1]), "+f"(c[2]), "+f"(c[3])
        : "r"(a[0]), "r"(a[1]), "r"(a[2]), "r"(a[3]), "r"(b0), "r"(b1));
}

// ---- cheap two-term split
__device__ __forceinline__ uint32_t pack_hi(float a, float b) {
    uint32_t r;
    asm("prmt.b32 %0, %1, %2, 0x7632;"
        : "=r"(r) : "r"(__float_as_uint(a)), "r"(__float_as_uint(b)));
    return r;
}
__device__ __forceinline__ float hi_f(float a) {
    return __uint_as_float(__float_as_uint(a) & 0xFFFF0000u);
}
__device__ __forceinline__ uint32_t pack_lo(float a, float b) {
    float la = a - hi_f(a), lb = b - hi_f(b);
    uint32_t r;
    asm("cvt.rn.bf16x2.f32 %0, %1, %2;" : "=r"(r) : "f"(lb), "f"(la));
    return r;
}

// ---------------------------------------------------------------------------
// Kernel 0: W split only (16 blocks, ~1.5us). nd table moved into gemm grid.
// ---------------------------------------------------------------------------
__global__ __launch_bounds__(256) void prep_w_kernel(const float* __restrict__ W)
{
    int t = blockIdx.x * 256 + threadIdx.x;
    if (t >= COUT * CIN / 8) return;
    const float4* src = (const float4*)W + t * 2;
    float4 f0 = src[0], f1 = src[1];
    uint4 hi, lo;
    hi.x = pack_hi(f0.x, f0.y); lo.x = pack_lo(f0.x, f0.y);
    hi.y = pack_hi(f0.z, f0.w); lo.y = pack_lo(f0.z, f0.w);
    hi.z = pack_hi(f1.x, f1.y); lo.z = pack_lo(f1.x, f1.y);
    hi.w = pack_hi(f1.z, f1.w); lo.w = pack_lo(f1.z, f1.w);
    *(uint4*)(g_Wh + t * 8) = hi;
    *(uint4*)(g_Wl + t * 8) = lo;
}

// ---------------------------------------------------------------------------
// Kernel 2: HMMA GEMM (R14/R16 config). Grid (NVB, NB+1): the extra y-row
// builds g_nd16 concurrently with the gemm wave (scatter launches after).
// ---------------------------------------------------------------------------
__global__ __launch_bounds__(512, 2)
void gemm_mma_kernel(const float* __restrict__ x, const float* __restrict__ bias,
                     const int* __restrict__ up, const int* __restrict__ down)
{
    // nd-prep blocks: blockIdx.y == NB
    if (blockIdx.y == NB) {
        int base = (blockIdx.x * 512 + threadIdx.x) * 2;
        #pragma unroll
        for (int e = 0; e < 2; e++) {
            int i = base + e;
            if (i < VRAW * 8) {
                int v = i >> 3, k = i & 7;
                int val = 0;
                if (k < 7) val = up[down[v] * 7 + k];
                g_nd16[i] = (unsigned short)val;
            }
        }
        return;
    }

    extern __shared__ char smem[];
    const uint32_t sbase = smem_u32(smem);
    const int tid  = threadIdx.x;
    const int lane = tid & 31;
    const int wid  = tid >> 5;            // 0..15
    const int b    = blockIdx.y;
    const int v0   = blockIdx.x * BNV;
    const int wo   = (wid >> 2) * 32;
    const int wv   = (wid & 3) * 32;
    const bool fullv = (v0 + BNV) <= VRAW;

    float acc[2][4][4];
    #pragma unroll
    for (int i = 0; i < 2; i++)
        #pragma unroll
        for (int j = 0; j < 4; j++)
            #pragma unroll
            for (int e = 0; e < 4; e++) acc[i][j][e] = 0.f;

    auto issueA = [&](int kc, int buf) {
        int o = tid >> 2, q = tid & 3;
        const __nv_bfloat16* sh = g_Wh + o * CIN + kc + q * 8;
        const __nv_bfloat16* sl = g_Wl + o * CIN + kc + q * 8;
        uint32_t dh = sbase + OFF_A + (buf * 2 + 0) * A_TILE + o * A_STRIDE + q * 16;
        cpa16(dh, sh);
        cpa16(dh + A_TILE, sl);
    };
    auto issueF = [&](int kc, int fb) {
        int c = tid >> 4, seg = tid & 15;
        const float* src = x + ((size_t)(b * CIN + kc + c)) * VRAW + v0 + seg * 8;
        uint32_t dst = sbase + OFF_F + fb * F_TILE + c * F_STRIDE + seg * 32;
        if (fullv) {
            #pragma unroll
            for (int j = 0; j < 4; j++) cpa8(dst + j * 8, src + j * 2);
        } else {
            #pragma unroll
            for (int j = 0; j < 4; j++) {
                int gv = v0 + seg * 8 + j * 2;
                uint32_t bytes = (gv + 2 <= VRAW) ? 8u : 0u;
                cpa8z(dst + j * 8, bytes ? (src + j * 2) : x, bytes);
            }
        }
    };
    auto convertB = [&](int buf) {
        int c = tid >> 4, seg = tid & 15;
        const char* fp = smem + OFF_F + (buf & 1) * F_TILE + c * F_STRIDE + seg * 32;
        float4 q0 = *(const float4*)(fp);
        float4 q1 = *(const float4*)(fp + 16);
        uint4 hi, lo;
        hi.x = pack_hi(q0.x, q0.y); lo.x = pack_lo(q0.x, q0.y);
        hi.y = pack_hi(q0.z, q0.w); lo.y = pack_lo(q0.z, q0.w);
        hi.z = pack_hi(q1.x, q1.y); lo.z = pack_lo(q1.x, q1.y);
        hi.w = pack_hi(q1.z, q1.w); lo.w = pack_lo(q1.z, q1.w);
        char* bh = smem + OFF_B + (buf * 2 + 0) * B_TILE + c * B_STRIDE + seg * 16;
        *(uint4*)(bh)          = hi;
        *(uint4*)(bh + B_TILE) = lo;
    };

    const int arow   = lane & 15;
    const int acol16 = (lane >> 4) * 16;
    const int brow   = ((lane >> 3) & 1) * 8 + (lane & 7);
    const int bcol16 = (lane >> 4) * 16;

    auto compute = [&](int buf) {
        uint32_t ah4 = sbase + OFF_A + (buf * 2) * A_TILE + (wo + arow) * A_STRIDE + acol16;
        uint32_t al4 = ah4 + A_TILE;
        uint32_t bh4 = sbase + OFF_B + (buf * 2) * B_TILE + brow * B_STRIDE + wv * 2 + bcol16;
        uint32_t bl4 = bh4 + B_TILE;
        #pragma unroll
        for (int ks = 0; ks < 2; ks++) {
            uint32_t a_h[2][4], a_l[2][4], b_h[2][4], b_l[2][4];
            #pragma unroll
            for (int mi = 0; mi < 2; mi++)
                ldsm4(a_h[mi], ah4 + mi * 16 * A_STRIDE + ks * 32);
            #pragma unroll
            for (int np = 0; np < 2; np++)
                ldsm4t(b_h[np], bh4 + ks * 16 * B_STRIDE + np * 32);
            #pragma unroll
            for (int mi = 0; mi < 2; mi++)
                #pragma unroll
                for (int nj = 0; nj < 4; nj++)
                    mma_bf16(acc[mi][nj], a_h[mi],
                             b_h[nj >> 1][(nj & 1) * 2], b_h[nj >> 1][(nj & 1) * 2 + 1]);
            #pragma unroll
            for (int np = 0; np < 2; np++)
                ldsm4t(b_l[np], bl4 + ks * 16 * B_STRIDE + np * 32);
            #pragma unroll
            for (int mi = 0; mi < 2; mi++)
                #pragma unroll
                for (int nj = 0; nj < 4; nj++)
                    mma_bf16(acc[mi][nj], a_h[mi],
                             b_l[nj >> 1][(nj & 1) * 2], b_l[nj >> 1][(nj & 1) * 2 + 1]);
            #pragma unroll
            for (int mi = 0; mi < 2; mi++)
                ldsm4(a_l[mi], al4 + mi * 16 * A_STRIDE + ks * 32);
            #pragma unroll
            for (int mi = 0; mi < 2; mi++)
                #pragma unroll
                for (int nj = 0; nj < 4; nj++)
                    mma_bf16(acc[mi][nj], a_l[mi],
                             b_h[nj >> 1][(nj & 1) * 2], b_h[nj >> 1][(nj & 1) * 2 + 1]);
        }
    };

    issueF(0, 0); issueA(0, 0); CP_COMMIT();
    for (int kt = 0; kt < NKCH; kt++) {
        int buf = kt & 1;
        if (kt + 1 < NKCH) {
            issueF((kt + 1) * BK, buf ^ 1);
            issueA((kt + 1) * BK, buf ^ 1);
            CP_COMMIT();
            CP_WAIT(1);
        } else {
            CP_WAIT(0);
        }
        convertB(buf);
        __syncthreads();
        compute(buf);
        __syncthreads();
    }

    #pragma unroll
    for (int mi = 0; mi < 2; mi++) {
        int o0 = wo + mi * 16 + (lane >> 2);
        float b0 = __ldg(&bias[o0]);
        float b1 = __ldg(&bias[o0 + 8]);
        float* h0 = g_h + ((size_t)b * COUT + o0) * VRAW;
        float* h1 = h0 + (size_t)8 * VRAW;
        #pragma unroll
        for (int nj = 0; nj < 4; nj++) {
            int gv = v0 + wv + nj * 8 + (lane & 3) * 2;
            if (gv < VRAW) {
                *(float2*)(h0 + gv) = make_float2(acc[mi][nj][0] + b0,
                                                  acc[mi][nj][1] + b0);
                *(float2*)(h1 + gv) = make_float2(acc[mi][nj][2] + b1,
                                                  acc[mi][nj][3] + b1);
            }
        }
    }
}

// ---------------------------------------------------------------------------
// Kernel 3: persistent scatter (R16 + int4 win reads on 16B-aligned rows).
// ---------------------------------------------------------------------------
__global__ __launch_bounds__(1024, 1) void scatter_kernel(
    const int* __restrict__ mpi, float* __restrict__ y)
{
    extern __shared__ int win[];      // NVERT ints
    const int tid = threadIdx.x;

    // one-time zero (epoch starts at 1, so 0 never matches)
    {
        int4* w4 = (int4*)win;
        int4 z = make_int4(0, 0, 0, 0);
        #pragma unroll
        for (int i = 0; i < 10; i++) w4[tid + (i << 10)] = z;
        if (tid < 2) win[40960 + tid] = 0;
    }

    int row = blockIdx.x;
    int epoch = 1;
    int vert[11];
    {   // startup: resolve first row's verts (exposed once)
        const int* mrow = mpi + (size_t)row * VRAW;
        int mk[11];
        #pragma unroll
        for (int i = 0; i < 11; i++) {
            int v = tid + (i << 10);
            mk[i] = (v < VRAW) ? __ldg(&mrow[v]) : 0;
        }
        #pragma unroll
        for (int i = 0; i < 11; i++) {
            int v = tid + (i << 10);
            vert[i] = (v < VRAW) ? (int)__ldg(&g_nd16[(v << 3) + mk[i]]) : 0;
        }
    }
    __syncthreads();

    while (row < NROWS) {
        const int tag = epoch << 14;
        // atomic phase: pure shared atomicMax
        #pragma unroll
        for (int i = 0; i < 11; i++) {
            int v = tid + (i << 10);
            if (v < VRAW) atomicMax(&win[vert[i]], tag | v);
        }

        // prefetch next row's mpi (LDGs fly over the barrier + write phase)
        int row2 = row + SC_GRID;
        int mk2[11];
        if (row2 < NROWS) {
            const int* mrow2 = mpi + (size_t)row2 * VRAW;
            #pragma unroll
            for (int i = 0; i < 11; i++) {
                int v = tid + (i << 10);
                mk2[i] = (v < VRAW) ? __ldg(&mrow2[v]) : 0;
            }
        }
        __syncthreads();   // atomics done before win reads

        // resolve next row's verts now — latency hides under the write loop
        if (row2 < NROWS) {
            #pragma unroll
            for (int i = 0; i < 11; i++) {
                int v = tid + (i << 10);
                vert[i] = (v < VRAW) ? (int)__ldg(&g_nd16[(v << 3) + mk2[i]]) : 0;
            }
        }

        // write phase: 10240 float4 quads + one pair at the ragged end
        const float* hrow = g_h + (size_t)row * VRAW;
        float* yrow = y + (size_t)row * NVERT;
        if (tid == 0) {
            int jp = (row & 1) ? 0 : 40960;
            int w0 = win[jp], w1 = win[jp + 1];
            float2 o;
            o.x = ((w0 >> 14) == epoch) ? __ldg(&hrow[w0 & 16383]) : 0.f;
            o.y = ((w1 >> 14) == epoch) ? __ldg(&hrow[w1 & 16383]) : 0.f;
            *(float2*)(yrow + jp) = o;
        }
        if ((row & 1) == 0) {
            // even row: quads start at 0, win reads 16B-aligned -> int4 LDS
            #pragma unroll
            for (int it = 0; it < 10; it++) {
                int q = tid + (it << 10);
                int j = q * 4;
                int4 w = *(const int4*)&win[j];
                float4 o;
                o.x = ((w.x >> 14) == epoch) ? __ldg(&hrow[w.x & 16383]) : 0.f;
                o.y = ((w.y >> 14) == epoch) ? __ldg(&hrow[w.y & 16383]) : 0.f;
                o.z = ((w.z >> 14) == epoch) ? __ldg(&hrow[w.z & 16383]) : 0.f;
                o.w = ((w.w >> 14) == epoch) ? __ldg(&hrow[w.w & 16383]) : 0.f;
                *(float4*)(yrow + j) = o;
            }
        } else {
            // odd row: quads start at 2 (y base ≡ 8 mod 16) -> int2 pairs
            #pragma unroll
            for (int it = 0; it < 10; it++) {
                int q = tid + (it << 10);
                int j = 2 + q * 4;
                int2 wa = *(const int2*)&win[j];
                int2 wb = *(const int2*)&win[j + 2];
                float4 o;
                o.x = ((wa.x >> 14) == epoch) ? __ldg(&hrow[wa.x & 16383]) : 0.f;
                o.y = ((wa.y >> 14) == epoch) ? __ldg(&hrow[wa.y & 16383]) : 0.f;
                o.z = ((wb.x >> 14) == epoch) ? __ldg(&hrow[wb.x & 16383]) : 0.f;
                o.w = ((wb.y >> 14) == epoch) ? __ldg(&hrow[wb.y & 16383]) : 0.f;
                *(float4*)(yrow + j) = o;
            }
        }
        __syncthreads();   // win reads done before next row's atomics

        row = row2;
        epoch++;
    }
}

// ---------------------------------------------------------------------------
extern "C" void kernel_launch(void* const* d_in, const int* in_sizes, int n_in,
                              void* d_out, int out_size)
{
    const float* x    = (const float*)d_in[0];
    const float* W    = (const float*)d_in[1];
    const float* bias = (const float*)d_in[2];
    const int*   up   = (const int*)d_in[3];
    const int*   down = (const int*)d_in[4];
    const int*   mpi  = (const int*)d_in[5];
    float* y = (float*)d_out;

    cudaFuncSetAttribute(scatter_kernel,
                         cudaFuncAttributeMaxDynamicSharedMemorySize, SC_SMEM);
    cudaFuncSetAttribute(gemm_mma_kernel,
                         cudaFuncAttributeMaxDynamicSharedMemorySize, SMEM_TOTAL);

    prep_w_kernel<<<(COUT * CIN / 8 + 255) / 256, 256>>>(W);

    dim3 g(NVB, NB + 1);   // 81 x 17: last y-row builds g_nd16 concurrently
    gemm_mma_kernel<<<g, 512, SMEM_TOTAL>>>(x, bias, up, down);

    scatter_kernel<<<SC_GRID, 1024, SC_SMEM>>>(mpi, y);
}